// round 3
// baseline (speedup 1.0000x reference)
#include <cuda_runtime.h>

#define MARGIN 9.0f
#define NB 32
#define NE 100000
#define ND 64
#define TPB 128
#define EPB 128
#define ROWF 68   // padded entity row stride (floats): conflict-free LDS.128 per 8-lane phase

typedef unsigned long long u64;

__device__ __forceinline__ u64 pack2(float x, float y) {
    u64 r; asm("mov.b64 %0, {%1, %2};" : "=l"(r) : "f"(x), "f"(y)); return r;
}
__device__ __forceinline__ void unpack2(u64 v, float& x, float& y) {
    asm("mov.b64 {%0, %1}, %2;" : "=f"(x), "=f"(y) : "l"(v));
}
// packed 2x fp32 FMA (sm_100+): d = a*b + d  elementwise on f32 pairs
__device__ __forceinline__ void ffma2(u64& d, u64 a, u64 b) {
    asm("fma.rn.f32x2 %0, %1, %2, %0;" : "+l"(d) : "l"(a), "l"(b));
}

__global__ void __launch_bounds__(TPB) transe_kernel(
    const void* __restrict__ subp, const void* __restrict__ relp,
    const float* __restrict__ emb_e, const float* __restrict__ emb_rel,
    float* __restrict__ out)
{
    __shared__ __align__(16) float qt[ND * NB];     // q transposed: [d][b]
    __shared__ float qn[NB];                        // ||q_b||^2
    __shared__ __align__(16) float es[EPB * ROWF];  // entity tile, padded rows

    const int tid = threadIdx.x;

    // ---- index dtype detection (jnp.int64 may have silently become int32) ----
    // Reading 8 int64 = 64 bytes is in-bounds for both layouts (int32 buffer is 128B).
    bool is64 = true;
    {
        const long long* s64 = (const long long*)subp;
        #pragma unroll
        for (int i = 0; i < 8; i++) {
            long long v = s64[i];
            if (v < 0 || v >= NE) is64 = false;
        }
    }

    // ---- build q^T in smem: qt[d*32 + b] = emb_e[sub[b]][d] + emb_rel[rel[b]][d] ----
    for (int i = tid; i < NB * ND; i += TPB) {
        int b = i & (NB - 1);
        int d = i >> 5;
        long long s = is64 ? ((const long long*)subp)[b] : (long long)((const int*)subp)[b];
        long long r = is64 ? ((const long long*)relp)[b] : (long long)((const int*)relp)[b];
        qt[d * NB + b] = emb_e[s * ND + d] + emb_rel[r * ND + d];
    }

    // ---- load 128-entity tile, coalesced float4, into padded smem rows ----
    long long ebase = (long long)blockIdx.x * EPB;
    const float4* src = (const float4*)emb_e;
    for (int i = tid; i < EPB * (ND / 4); i += TPB) {
        int row = i >> 4;     // 16 float4 per row
        int c   = i & 15;
        long long ge = ebase + row;
        float4 v = make_float4(0.f, 0.f, 0.f, 0.f);
        if (ge < NE) v = src[ge * (ND / 4) + c];
        *(float4*)&es[row * ROWF + c * 4] = v;
    }
    __syncthreads();

    // ---- ||q_b||^2: warp 0, lane b; reads qt[d*32 + lane] => consecutive => conflict-free ----
    if (tid < NB) {
        float s = 0.f;
        #pragma unroll
        for (int d = 0; d < ND; d++) { float v = qt[d * NB + tid]; s = fmaf(v, v, s); }
        qn[tid] = s;
    }
    __syncthreads();

    // ---- main accumulation: each thread owns one entity ----
    // acc[p] holds packed (b=2p, b=2p+1); init -qn/2 so dist^2 = en - 2*acc at the end.
    u64 acc[NB / 2];
    #pragma unroll
    for (int p = 0; p < NB / 2; p++)
        acc[p] = pack2(-0.5f * qn[2 * p], -0.5f * qn[2 * p + 1]);

    float en = 0.f;
    const float* myrow = &es[tid * ROWF];

    #pragma unroll 2
    for (int c = 0; c < ND / 4; c++) {
        float4 ev = *(const float4*)&myrow[c * 4];   // LDS.128, phase-conflict-free
        en = fmaf(ev.x, ev.x, en);
        en = fmaf(ev.y, ev.y, en);
        en = fmaf(ev.z, ev.z, en);
        en = fmaf(ev.w, ev.w, en);
        u64 ed[4];
        ed[0] = pack2(ev.x, ev.x);
        ed[1] = pack2(ev.y, ev.y);
        ed[2] = pack2(ev.z, ev.z);
        ed[3] = pack2(ev.w, ev.w);
        #pragma unroll
        for (int k = 0; k < 4; k++) {
            // qt row for dim d = 4c+k: 32 floats = 8 x ulonglong2 (each = 2 packed b-pairs)
            const ulonglong2* qrow = (const ulonglong2*)&qt[(4 * c + k) * NB];
            #pragma unroll
            for (int j = 0; j < 8; j++) {
                ulonglong2 qq = qrow[j];             // LDS.128 broadcast (free, N=1)
                ffma2(acc[2 * j],     ed[k], qq.x);
                ffma2(acc[2 * j + 1], ed[k], qq.y);
            }
        }
    }

    // ---- epilogue: dist^2 = en - 2*acc ; out = MARGIN - sqrt(dist^2) ----
    long long e = ebase + tid;
    if (e < NE) {
        #pragma unroll
        for (int p = 0; p < NB / 2; p++) {
            float a0, a1; unpack2(acc[p], a0, a1);
            float d0 = fmaxf(en - 2.f * a0, 0.f);
            float d1 = fmaxf(en - 2.f * a1, 0.f);
            out[(long long)(2 * p) * NE + e]     = MARGIN - sqrtf(d0);  // coalesced across lanes
            out[(long long)(2 * p + 1) * NE + e] = MARGIN - sqrtf(d1);
        }
    }
}

extern "C" void kernel_launch(void* const* d_in, const int* in_sizes, int n_in,
                              void* d_out, int out_size) {
    (void)in_sizes; (void)n_in; (void)out_size;
    const void* sub      = d_in[0];
    const void* rel      = d_in[1];
    const float* emb_e   = (const float*)d_in[2];
    const float* emb_rel = (const float*)d_in[3];
    float* out = (float*)d_out;

    int grid = (NE + EPB - 1) / EPB;   // 782 blocks
    transe_kernel<<<grid, TPB>>>(sub, rel, emb_e, emb_rel, out);
}

// round 4
// speedup vs baseline: 1.4640x; 1.4640x over previous
#include <cuda_runtime.h>

#define MARGIN 9.0f
#define NB  32
#define NEI 100000
#define ND  64
#define TPB 256
#define EPB 256

typedef unsigned long long u64;

__device__ __forceinline__ u64 pack2(float x, float y) {
    u64 r; asm("mov.b64 %0, {%1, %2};" : "=l"(r) : "f"(x), "f"(y)); return r;
}
__device__ __forceinline__ void unpack2(u64 v, float& x, float& y) {
    asm("mov.b64 {%0, %1}, %2;" : "=f"(x), "=f"(y) : "l"(v));
}
// packed 2x fp32 FMA (sm_100+): d = a*b + d elementwise on f32 pairs
__device__ __forceinline__ void ffma2(u64& d, u64 a, u64 b) {
    asm("fma.rn.f32x2 %0, %1, %2, %0;" : "+l"(d) : "l"(a), "l"(b));
}

extern __shared__ __align__(16) unsigned char smem_raw[];

// smem layout (dynamic, 83072 B):
//   est   [ND][EPB] float  : 65536 B  (entity tile, transposed: d-major)
//   qsp   [ND][NB]  u64    : 16384 B  (q pre-splatted: (q,q) pairs)
//   enorm [EPB]     float  :  1024 B
//   qn    [NB]      float  :   128 B
#define SMEM_BYTES (ND*EPB*4 + ND*NB*8 + EPB*4 + NB*4)

__global__ void __launch_bounds__(TPB, 2) transe_kernel(
    const void* __restrict__ subp, const void* __restrict__ relp,
    const float* __restrict__ emb_e, const float* __restrict__ emb_rel,
    float* __restrict__ out)
{
    float* est   = (float*)smem_raw;
    u64*   qsp   = (u64*)(smem_raw + ND * EPB * 4);
    float* enorm = (float*)(smem_raw + ND * EPB * 4 + ND * NB * 8);
    float* qn    = enorm + EPB;

    const int tid = threadIdx.x;

    // ---- index dtype detection (jnp.int64 may silently be int32) ----
    // Reading 8 int64 = 64B is in-bounds for both layouts (int32 buffer is 128B).
    bool is64 = true;
    {
        const long long* s64 = (const long long*)subp;
        #pragma unroll
        for (int i = 0; i < 8; i++) {
            long long v = s64[i];
            if (v < 0 || v >= NEI) is64 = false;
        }
    }

    // ---- q fill: qsp[d][b] = splat(emb_e[sub[b]][d] + emb_rel[rel[b]][d]) ----
    // 512 float4 jobs (32 b x 16 c), 2 per thread; b = j&31 keeps STS ~conflict-free.
    #pragma unroll
    for (int it = 0; it < 2; it++) {
        int j = tid + it * TPB;
        int b = j & 31;
        int c = j >> 5;            // 0..15
        long long s = is64 ? ((const long long*)subp)[b] : (long long)((const int*)subp)[b];
        long long r = is64 ? ((const long long*)relp)[b] : (long long)((const int*)relp)[b];
        float4 ve = ((const float4*)emb_e)[s * (ND/4) + c];
        float4 vr = ((const float4*)emb_rel)[r * (ND/4) + c];
        float q0 = ve.x + vr.x, q1 = ve.y + vr.y, q2 = ve.z + vr.z, q3 = ve.w + vr.w;
        qsp[(4*c + 0) * NB + b] = pack2(q0, q0);
        qsp[(4*c + 1) * NB + b] = pack2(q1, q1);
        qsp[(4*c + 2) * NB + b] = pack2(q2, q2);
        qsp[(4*c + 3) * NB + b] = pack2(q3, q3);
    }

    // ---- entity tile fill (transposed) + per-entity norms ----
    long long ebase = (long long)blockIdx.x * EPB;
    {
        long long ge = ebase + tid;
        const float4* src = (const float4*)emb_e;
        float nrm = 0.f;
        #pragma unroll
        for (int c = 0; c < ND/4; c++) {
            float4 v = make_float4(0.f, 0.f, 0.f, 0.f);
            if (ge < NEI) v = src[ge * (ND/4) + c];
            est[(4*c + 0) * EPB + tid] = v.x;   // STS: lanes -> distinct e -> distinct banks
            est[(4*c + 1) * EPB + tid] = v.y;
            est[(4*c + 2) * EPB + tid] = v.z;
            est[(4*c + 3) * EPB + tid] = v.w;
            nrm = fmaf(v.x, v.x, fmaf(v.y, v.y, fmaf(v.z, v.z, fmaf(v.w, v.w, nrm))));
        }
        enorm[tid] = nrm;
    }
    __syncthreads();

    // ---- ||q_b||^2 by warp 0 ----
    if (tid < NB) {
        float s = 0.f;
        #pragma unroll
        for (int d = 0; d < ND; d++) {
            float x, y; unpack2(qsp[d * NB + tid], x, y);
            s = fmaf(x, x, s);
        }
        qn[tid] = s;
    }
    __syncthreads();

    // ---- thread tile: bg owns 4 b-rows, eg owns 8 entity-cols (XOR-swizzled) ----
    const int bg = tid >> 5;            // 0..7  (whole warp shares bg -> q reads broadcast)
    const int eg = tid & 31;            // 0..31
    const int s4 = (eg & 4) ? 4 : 0;    // XOR swizzle: removes 2-way bank conflict
    const int cA = eg * 8 + s4;         // first 4 columns
    const int cB = eg * 8 + 4 - s4;     // other 4 columns

    // acc[b][ep] accumulates dot(q_b, e); init with -0.5*(qn+en) so dist^2 = -2*acc
    u64 acc[4][4];
    {
        float eA0 = enorm[cA], eA1 = enorm[cA+1], eA2 = enorm[cA+2], eA3 = enorm[cA+3];
        float eB0 = enorm[cB], eB1 = enorm[cB+1], eB2 = enorm[cB+2], eB3 = enorm[cB+3];
        #pragma unroll
        for (int bi = 0; bi < 4; bi++) {
            float qb = qn[bg * 4 + bi];
            acc[bi][0] = pack2(-0.5f*(qb+eA0), -0.5f*(qb+eA1));
            acc[bi][1] = pack2(-0.5f*(qb+eA2), -0.5f*(qb+eA3));
            acc[bi][2] = pack2(-0.5f*(qb+eB0), -0.5f*(qb+eB1));
            acc[bi][3] = pack2(-0.5f*(qb+eB2), -0.5f*(qb+eB3));
        }
    }

    // ---- main loop: per d, 4 LDS.128 + 16 independent ffma2 ----
    #pragma unroll 8
    for (int d = 0; d < ND; d++) {
        ulonglong2 q01 = *(const ulonglong2*)(qsp + d * NB + bg * 4);      // broadcast
        ulonglong2 q23 = *(const ulonglong2*)(qsp + d * NB + bg * 4 + 2);  // broadcast
        ulonglong2 ea  = *(const ulonglong2*)(est + d * EPB + cA);         // conflict-free
        ulonglong2 eb  = *(const ulonglong2*)(est + d * EPB + cB);         // conflict-free
        u64 qv0 = q01.x, qv1 = q01.y, qv2 = q23.x, qv3 = q23.y;
        ffma2(acc[0][0], ea.x, qv0); ffma2(acc[0][1], ea.y, qv0);
        ffma2(acc[0][2], eb.x, qv0); ffma2(acc[0][3], eb.y, qv0);
        ffma2(acc[1][0], ea.x, qv1); ffma2(acc[1][1], ea.y, qv1);
        ffma2(acc[1][2], eb.x, qv1); ffma2(acc[1][3], eb.y, qv1);
        ffma2(acc[2][0], ea.x, qv2); ffma2(acc[2][1], ea.y, qv2);
        ffma2(acc[2][2], eb.x, qv2); ffma2(acc[2][3], eb.y, qv2);
        ffma2(acc[3][0], ea.x, qv3); ffma2(acc[3][1], ea.y, qv3);
        ffma2(acc[3][2], eb.x, qv3); ffma2(acc[3][3], eb.y, qv3);
    }

    // ---- epilogue: out = MARGIN - sqrt(max(-2*acc, 0)) ----
    long long rem = NEI - ebase;                 // >0 always
    bool full = (eg * 8 + 8 <= rem);
    #pragma unroll
    for (int bi = 0; bi < 4; bi++) {
        float oA[4], oB[4];
        #pragma unroll
        for (int ep = 0; ep < 2; ep++) {
            float a0, a1;
            unpack2(acc[bi][ep], a0, a1);
            oA[2*ep]   = MARGIN - sqrtf(fmaxf(-2.f * a0, 0.f));
            oA[2*ep+1] = MARGIN - sqrtf(fmaxf(-2.f * a1, 0.f));
            unpack2(acc[bi][2 + ep], a0, a1);
            oB[2*ep]   = MARGIN - sqrtf(fmaxf(-2.f * a0, 0.f));
            oB[2*ep+1] = MARGIN - sqrtf(fmaxf(-2.f * a1, 0.f));
        }
        float* orow = out + (long long)(bg * 4 + bi) * NEI + ebase;
        if (full) {
            *(float4*)(orow + cA) = make_float4(oA[0], oA[1], oA[2], oA[3]);
            *(float4*)(orow + cB) = make_float4(oB[0], oB[1], oB[2], oB[3]);
        } else {
            #pragma unroll
            for (int j = 0; j < 4; j++) {
                if (cA + j < rem) orow[cA + j] = oA[j];
                if (cB + j < rem) orow[cB + j] = oB[j];
            }
        }
    }
}

extern "C" void kernel_launch(void* const* d_in, const int* in_sizes, int n_in,
                              void* d_out, int out_size) {
    (void)in_sizes; (void)n_in; (void)out_size;
    const void* sub      = d_in[0];
    const void* rel      = d_in[1];
    const float* emb_e   = (const float*)d_in[2];
    const float* emb_rel = (const float*)d_in[3];
    float* out = (float*)d_out;

    static bool attr_set = false;   // idempotent attribute set (not a memory alloc)
    if (!attr_set) {
        cudaFuncSetAttribute(transe_kernel,
                             cudaFuncAttributeMaxDynamicSharedMemorySize, SMEM_BYTES);
        attr_set = true;
    }

    int grid = (NEI + EPB - 1) / EPB;   // 391 blocks
    transe_kernel<<<grid, TPB, SMEM_BYTES>>>(sub, rel, emb_e, emb_rel, out);
}